// round 1
// baseline (speedup 1.0000x reference)
#include <cuda_runtime.h>
#include <cuda_bf16.h>
#include <math.h>

// Problem constants (GCNAggregator): B=4096, K=32, U=32768, V=100000, D=128
#define GCN_B 4096
#define GCN_K 32
#define GCN_U 32768
#define GCN_D 128

// Scratch (no cudaMalloc allowed)
__device__ int      g_col_deg[GCN_U];
__device__ float    g_col_scale[GCN_U];
__device__ unsigned g_row_mask[GCN_B];   // bit k set = k-th entry is first occurrence in its row

// ---------------------------------------------------------------------------
// Kernel 1: zero column degrees
// ---------------------------------------------------------------------------
__global__ void zero_col_deg_kernel() {
    int u = blockIdx.x * blockDim.x + threadIdx.x;
    if (u < GCN_U) g_col_deg[u] = 0;
}

// ---------------------------------------------------------------------------
// Kernel 2: per-row dedupe (one warp per row) + column degree accumulation
// ---------------------------------------------------------------------------
__global__ void dedupe_degree_kernel(const int* __restrict__ neigh_cols) {
    int warp_in_block = threadIdx.x >> 5;
    int lane = threadIdx.x & 31;
    int b = blockIdx.x * (blockDim.x >> 5) + warp_in_block;
    if (b >= GCN_B) return;

    int c = neigh_cols[b * GCN_K + lane];

    // first occurrence check: no lane j < lane holds the same column
    bool first = true;
    #pragma unroll
    for (int j = 0; j < GCN_K; j++) {
        int cj = __shfl_sync(0xFFFFFFFFu, c, j);
        if (j < lane && cj == c) first = false;
    }

    unsigned mask = __ballot_sync(0xFFFFFFFFu, first);
    if (lane == 0) g_row_mask[b] = mask;
    if (first) atomicAdd(&g_col_deg[c], 1);
}

// ---------------------------------------------------------------------------
// Kernel 3: column scale = 1 / max(sqrt(deg), 1)
// ---------------------------------------------------------------------------
__global__ void col_scale_kernel() {
    int u = blockIdx.x * blockDim.x + threadIdx.x;
    if (u < GCN_U) {
        float deg = (float)g_col_deg[u];
        g_col_scale[u] = 1.0f / fmaxf(sqrtf(deg), 1.0f);
    }
}

// ---------------------------------------------------------------------------
// Kernel 4: aggregation. One block per row, 128 threads (one per feature dim).
// Branch-free 32-term weighted gather: duplicate entries carry weight 0.
// ---------------------------------------------------------------------------
__global__ void __launch_bounds__(GCN_D)
aggregate_kernel(const int* __restrict__ neigh_cols,
                 const int* __restrict__ unique_ids,
                 const float* __restrict__ embed_table,
                 float* __restrict__ out) {
    int b = blockIdx.x;
    int d = threadIdx.x;

    __shared__ float s_w[GCN_K];
    __shared__ int   s_off[GCN_K];   // row offset into embed_table (elements)

    unsigned mask = g_row_mask[b];
    if (d < GCN_K) {
        int c = neigh_cols[b * GCN_K + d];
        bool first = (mask >> d) & 1u;
        s_w[d]   = first ? g_col_scale[c] : 0.0f;
        s_off[d] = unique_ids[c] * GCN_D;
    }
    __syncthreads();

    float acc = 0.0f;
    #pragma unroll
    for (int k = 0; k < GCN_K; k++) {
        acc = fmaf(s_w[k], __ldg(&embed_table[s_off[k] + d]), acc);
    }

    float row_scale = 1.0f / sqrtf((float)__popc(mask));
    out[b * GCN_D + d] = row_scale * acc;
}

// ---------------------------------------------------------------------------
extern "C" void kernel_launch(void* const* d_in, const int* in_sizes, int n_in,
                              void* d_out, int out_size) {
    const int*   neigh_cols  = (const int*)d_in[0];
    const int*   unique_ids  = (const int*)d_in[1];
    const float* embed_table = (const float*)d_in[2];
    float*       out         = (float*)d_out;

    zero_col_deg_kernel<<<(GCN_U + 255) / 256, 256>>>();
    dedupe_degree_kernel<<<GCN_B / 8, 256>>>(neigh_cols);
    col_scale_kernel<<<(GCN_U + 255) / 256, 256>>>();
    aggregate_kernel<<<GCN_B, GCN_D>>>(neigh_cols, unique_ids, embed_table, out);
}

// round 2
// speedup vs baseline: 1.1407x; 1.1407x over previous
#include <cuda_runtime.h>
#include <cuda_bf16.h>
#include <math.h>

// Problem constants (GCNAggregator): B=4096, K=32, U=32768, V=100000, D=128
#define GCN_B 4096
#define GCN_K 32
#define GCN_U 32768
#define GCN_D 128
#define ROWS_PER_BLOCK 4

// Scratch (no cudaMalloc allowed)
__device__ int      g_col_deg[GCN_U];
__device__ unsigned g_row_mask[GCN_B];   // bit k set = k-th entry is first occurrence in its row

// ---------------------------------------------------------------------------
// Kernel 1: zero column degrees
// ---------------------------------------------------------------------------
__global__ void zero_col_deg_kernel() {
    int u = blockIdx.x * blockDim.x + threadIdx.x;
    if (u < GCN_U) g_col_deg[u] = 0;
}

// ---------------------------------------------------------------------------
// Kernel 2: per-row dedupe (one warp per row) + column degree accumulation
// ---------------------------------------------------------------------------
__global__ void dedupe_degree_kernel(const int* __restrict__ neigh_cols) {
    int warp_in_block = threadIdx.x >> 5;
    int lane = threadIdx.x & 31;
    int b = blockIdx.x * (blockDim.x >> 5) + warp_in_block;
    if (b >= GCN_B) return;

    int c = neigh_cols[b * GCN_K + lane];

    // first occurrence: no lane j < lane holds the same column
    bool first = true;
    #pragma unroll
    for (int j = 0; j < GCN_K; j++) {
        int cj = __shfl_sync(0xFFFFFFFFu, c, j);
        if (j < lane && cj == c) first = false;
    }

    unsigned mask = __ballot_sync(0xFFFFFFFFu, first);
    if (lane == 0) g_row_mask[b] = mask;
    if (first) atomicAdd(&g_col_deg[c], 1);
}

// ---------------------------------------------------------------------------
// Kernel 3 (fused agg): one WARP per row, each lane owns 4 consecutive dims.
// 32 x LDG.128 per thread; (offset, weight) packed as int2 -> one LDS.64 per k.
// Duplicates carry weight 0 -> branch-free fully-unrolled gather.
// ---------------------------------------------------------------------------
__global__ void __launch_bounds__(32 * ROWS_PER_BLOCK)
aggregate_kernel(const int* __restrict__ neigh_cols,
                 const int* __restrict__ unique_ids,
                 const float4* __restrict__ embed_table4,  // [V, 32] float4
                 float4* __restrict__ out4) {              // [B, 32] float4
    int warp = threadIdx.x >> 5;
    int lane = threadIdx.x & 31;
    int b = blockIdx.x * ROWS_PER_BLOCK + warp;

    __shared__ int2 s_wo[ROWS_PER_BLOCK][GCN_K];  // {off4, bitcast(w)}

    unsigned mask = g_row_mask[b];
    {
        int c = neigh_cols[b * GCN_K + lane];
        bool first = (mask >> lane) & 1u;
        float w = 0.0f;
        if (first) {
            float deg = (float)g_col_deg[c];
            w = 1.0f / fmaxf(sqrtf(deg), 1.0f);
        }
        int off4 = unique_ids[c] * (GCN_D / 4);  // row offset in float4 units
        s_wo[warp][lane] = make_int2(off4, __float_as_int(w));
    }
    __syncwarp();

    float4 acc = make_float4(0.f, 0.f, 0.f, 0.f);
    #pragma unroll
    for (int k = 0; k < GCN_K; k++) {
        int2 wo = s_wo[warp][k];
        float w = __int_as_float(wo.y);
        float4 v = __ldg(&embed_table4[wo.x + lane]);
        acc.x = fmaf(w, v.x, acc.x);
        acc.y = fmaf(w, v.y, acc.y);
        acc.z = fmaf(w, v.z, acc.z);
        acc.w = fmaf(w, v.w, acc.w);
    }

    float rs = 1.0f / sqrtf((float)__popc(mask));
    acc.x *= rs; acc.y *= rs; acc.z *= rs; acc.w *= rs;
    out4[b * (GCN_D / 4) + lane] = acc;
}

// ---------------------------------------------------------------------------
extern "C" void kernel_launch(void* const* d_in, const int* in_sizes, int n_in,
                              void* d_out, int out_size) {
    const int*    neigh_cols   = (const int*)d_in[0];
    const int*    unique_ids   = (const int*)d_in[1];
    const float4* embed_table4 = (const float4*)d_in[2];
    float4*       out4         = (float4*)d_out;

    zero_col_deg_kernel<<<(GCN_U + 255) / 256, 256>>>();
    dedupe_degree_kernel<<<GCN_B / 8, 256>>>(neigh_cols);
    aggregate_kernel<<<GCN_B / ROWS_PER_BLOCK, 32 * ROWS_PER_BLOCK>>>(
        neigh_cols, unique_ids, embed_table4, out4);
}